// round 7
// baseline (speedup 1.0000x reference)
#include <cuda_runtime.h>
#include <math.h>
#include <stdint.h>

// ---------------- constants ----------------
#define SEQ    1024
#define DMODEL 1024
#define NHEAD  16
#define NKV    2
#define HDIM   64
#define FFDIM  2560
#define KVLEN  2048
#define LTOT   16
#define RSCALE 0.35355339059327373f   // 64^-0.25

// ---------------- scratch ----------------
__device__ float g_h[SEQ * DMODEL];
__device__ float g_x[SEQ * DMODEL];
__device__ float g_q[SEQ * DMODEL];          // q, later attn-out
__device__ float g_k[SEQ * NKV * HDIM];
__device__ float g_v[SEQ * NKV * HDIM];
__device__ float g_gate[SEQ * FFDIM];
__device__ float g_up[SEQ * FFDIM];
__device__ float g_scores[NHEAD * SEQ * KVLEN];   // 134 MB
__device__ float g_z[768 * 32];
__device__ float g_f[768 * DMODEL];
__device__ float g_lmh[DMODEL];
__device__ float g_rh[DMODEL];
__device__ float g_sp[DMODEL];
__device__ float g_cos[SEQ * 32];
__device__ float g_sin[SEQ * 32];

// ---------------- SGEMM ----------------
// C[M,N] (+)= A[M,K] @ B[K,N], row-major with leading dims, batched over z.
// A_z = A + z*sA ; B_z = B + (z/bdiv)*sB ; C_z = C + z*sC
// Block tile 64x64, BK=16, 256 threads, 4x4 microtile.
__global__ __launch_bounds__(256) void sgemm(
    const float* __restrict__ A, int lda, long sA,
    const float* __restrict__ B, int ldb, long sB, int bdiv,
    float* __restrict__ C, int ldc, long sC,
    int M, int N, int K, int addTo)
{
    __shared__ float As[16][68];   // [k][m]
    __shared__ float Bs[16][68];   // [k][n]
    int z = blockIdx.z;
    A += (long)z * sA;
    B += (long)(z / bdiv) * sB;
    C += (long)z * sC;
    int bm = blockIdx.y * 64, bn = blockIdx.x * 64;
    int tid = threadIdx.x;
    int ty = tid >> 4, tx = tid & 15;
    int ar = tid >> 2,  ac = (tid & 3) << 2;    // A loader: row 0..63, k-off 0/4/8/12
    int br = tid >> 4,  bc = (tid & 15) << 2;   // B loader: k 0..15, n-off 0..60

    float acc[4][4] = {};
    for (int k0 = 0; k0 < K; k0 += 16) {
        float4 a4 = *(const float4*)(A + (long)(bm + ar) * lda + (k0 + ac));
        As[ac+0][ar] = a4.x; As[ac+1][ar] = a4.y;
        As[ac+2][ar] = a4.z; As[ac+3][ar] = a4.w;
        float4 b4;
        if (bn + bc < N) b4 = *(const float4*)(B + (long)(k0 + br) * ldb + (bn + bc));
        else             b4 = make_float4(0.f, 0.f, 0.f, 0.f);
        *(float4*)&Bs[br][bc] = b4;
        __syncthreads();
        #pragma unroll
        for (int kk = 0; kk < 16; kk++) {
            float4 av = *(const float4*)&As[kk][ty << 2];
            float4 bv = *(const float4*)&Bs[kk][tx << 2];
            acc[0][0] += av.x * bv.x; acc[0][1] += av.x * bv.y;
            acc[0][2] += av.x * bv.z; acc[0][3] += av.x * bv.w;
            acc[1][0] += av.y * bv.x; acc[1][1] += av.y * bv.y;
            acc[1][2] += av.y * bv.z; acc[1][3] += av.y * bv.w;
            acc[2][0] += av.z * bv.x; acc[2][1] += av.z * bv.y;
            acc[2][2] += av.z * bv.z; acc[2][3] += av.z * bv.w;
            acc[3][0] += av.w * bv.x; acc[3][1] += av.w * bv.y;
            acc[3][2] += av.w * bv.z; acc[3][3] += av.w * bv.w;
        }
        __syncthreads();
    }
    int m0 = bm + (ty << 2), n0 = bn + (tx << 2);
    if (n0 < N) {
        #pragma unroll
        for (int i = 0; i < 4; i++) {
            float* cp = C + (long)(m0 + i) * ldc + n0;
            float4 cv = make_float4(acc[i][0], acc[i][1], acc[i][2], acc[i][3]);
            if (addTo) {
                float4 o = *(const float4*)cp;
                cv.x += o.x; cv.y += o.y; cv.z += o.z; cv.w += o.w;
            }
            *(float4*)cp = cv;
        }
    }
}

// ---------------- RMSNorm (D=1024) ----------------
__global__ __launch_bounds__(256) void rms_rows(
    const float* __restrict__ x, const float* __restrict__ w, float* __restrict__ o)
{
    long r = blockIdx.x;
    const float4* xr = (const float4*)(x + r * DMODEL);
    float4* orow = (float4*)(o + r * DMODEL);
    int tid = threadIdx.x;
    float4 v = xr[tid];
    float ss = v.x*v.x + v.y*v.y + v.z*v.z + v.w*v.w;
    __shared__ float red[256];
    red[tid] = ss; __syncthreads();
    for (int of = 128; of > 0; of >>= 1) {
        if (tid < of) red[tid] += red[tid + of];
        __syncthreads();
    }
    float scale = rsqrtf(red[0] * (1.0f / DMODEL) + 1e-5f);
    float4 ww = ((const float4*)w)[tid];
    orow[tid] = make_float4(v.x*scale*ww.x, v.y*scale*ww.y, v.z*scale*ww.z, v.w*scale*ww.w);
}

// ---------------- RoPE tables (double-precision angles) ----------------
__global__ void rope_tab(float* gc, float* gs) {
    int t = blockIdx.x, i = threadIdx.x;  // 1024 x 32
    double inv = exp(-(double)i * (9.210340371976184 / 32.0));  // 10000^(-i/32)
    double ang = (double)(1024 + t) * inv;
    gc[t*32 + i] = (float)cos(ang) * RSCALE;
    gs[t*32 + i] = (float)sin(ang) * RSCALE;
}

// ---------------- RoPE apply + scatter K/V into output cache ----------------
__global__ __launch_bounds__(128) void rope_scatter(
    float* __restrict__ q, const float* __restrict__ k, const float* __restrict__ v,
    float* __restrict__ oK, float* __restrict__ oV,
    const float* __restrict__ gc, const float* __restrict__ gs)
{
    int t = blockIdx.x, tid = threadIdx.x;
    #pragma unroll
    for (int p = tid; p < 512; p += 128) {
        int h = p >> 5, i = p & 31;
        float c = gc[t*32 + i], s = gs[t*32 + i];
        int b = t*DMODEL + h*64 + i;
        float x1 = q[b], x2 = q[b + 32];
        q[b]      = x1*c - x2*s;
        q[b + 32] = x2*c + x1*s;
    }
    if (tid < 64) {
        int kv = tid >> 5, i = tid & 31;
        float c = gc[t*32 + i], s = gs[t*32 + i];
        int b = t*128 + kv*64 + i;
        float x1 = k[b], x2 = k[b + 32];
        oK[(long)(kv*64 + i     ) * KVLEN + 1024 + t] = x1*c - x2*s;
        oK[(long)(kv*64 + i + 32) * KVLEN + 1024 + t] = x2*c + x1*s;
    }
    {
        int kv = tid >> 6;
        int d  = tid & 63;
        oV[(long)(kv*KVLEN + 1024 + t) * 64 + d] = v[t*128 + tid];
    }
}

// ---------------- softmax with mask over 2048 cols ----------------
__global__ __launch_bounds__(256) void softmax_mask(float* __restrict__ S,
                                                    const float* __restrict__ mf)
{
    long r = blockIdx.x;            // h*1024 + t
    int t = (int)(r & 1023);
    float flag = mf[0];
    float* row = S + r * KVLEN;
    int tid = threadIdx.x;
    float vals[8];
    float mx = -1e30f;
    #pragma unroll
    for (int j = 0; j < 8; j++) {
        int s = tid + j*256;
        float m = (s > t) ? (-128.0f * flag) : 0.0f;
        vals[j] = row[s] + m;
        mx = fmaxf(mx, vals[j]);
    }
    __shared__ float red[256];
    red[tid] = mx; __syncthreads();
    for (int of = 128; of > 0; of >>= 1) {
        if (tid < of) red[tid] = fmaxf(red[tid], red[tid + of]);
        __syncthreads();
    }
    mx = red[0]; __syncthreads();
    float sum = 0.f;
    #pragma unroll
    for (int j = 0; j < 8; j++) { vals[j] = expf(vals[j] - mx); sum += vals[j]; }
    red[tid] = sum; __syncthreads();
    for (int of = 128; of > 0; of >>= 1) {
        if (tid < of) red[tid] += red[tid + of];
        __syncthreads();
    }
    float inv = 1.0f / red[0];
    #pragma unroll
    for (int j = 0; j < 8; j++) row[tid + j*256] = vals[j] * inv;
}

// ---------------- elementwise ----------------
__global__ void silu_mul(float* __restrict__ g, const float* __restrict__ u, int n4) {
    int i = blockIdx.x * blockDim.x + threadIdx.x;
    if (i >= n4) return;
    float4 a = ((float4*)g)[i];
    float4 b = ((const float4*)u)[i];
    a.x = a.x / (1.f + expf(-a.x)) * b.x;
    a.y = a.y / (1.f + expf(-a.y)) * b.y;
    a.z = a.z / (1.f + expf(-a.z)) * b.z;
    a.w = a.w / (1.f + expf(-a.w)) * b.w;
    ((float4*)g)[i] = a;
}

__global__ void tanh_quant(float* z, int n) {
    int i = blockIdx.x * blockDim.x + threadIdx.x;
    if (i >= n) return;
    float t = tanhf(z[i]);
    float r = rintf(t * 4.0f) * 0.25f;   // round half-to-even like jnp.round
    z[i] = t + (r - t);
}

__global__ void copy_f4(float* __restrict__ dst, const float* __restrict__ src, int n4) {
    int i = blockIdx.x * blockDim.x + threadIdx.x;
    if (i < n4) ((float4*)dst)[i] = ((const float4*)src)[i];
}

// h[0:256] = x[0:256]; h[256:1024] = f + feat; also grab lm_hidden = f[767]
__global__ void build_h(float* __restrict__ h, const float* __restrict__ x,
                        const float* __restrict__ f, const float* __restrict__ feat,
                        float* __restrict__ lmh)
{
    int i = blockIdx.x * 256 + threadIdx.x;   // 1,048,576
    int row = i >> 10, col = i & 1023;
    if (row < 256) h[i] = x[i];
    else {
        int j = ((row - 256) << 10) + col;
        h[i] = f[j] + feat[j];
    }
    if (row == 1023) lmh[col] = f[(767 << 10) + col];
}

// ---------------- history cache copy into d_out ----------------
__global__ void copy_caches(const float* __restrict__ kc, const float* __restrict__ vc,
                            float* __restrict__ oK, float* __restrict__ oV)
{
    int i = blockIdx.x * 256 + threadIdx.x;      // 1,048,576 float4 jobs
    if (i < 524288) {                            // K: rows of 1024 -> rows of 2048
        int row = i >> 8, c4 = i & 255;
        ((float4*)oK)[(long)row * 512 + c4] = ((const float4*)kc)[i];
    } else {                                     // V: per (l,kv) 65536 floats contiguous
        int j = i - 524288;
        int pair = j >> 14, off = j & 16383;
        ((float4*)oV)[(long)pair * 32768 + off] = ((const float4*)vc)[j];
    }
}

// ---------------- small heads ----------------
__global__ void gemv_dit(const float* __restrict__ lmh, const float* __restrict__ rh,
                         const float* __restrict__ W1, const float* __restrict__ W2,
                         float* __restrict__ out)
{
    int n = blockIdx.x * 256 + threadIdx.x;   // 1024
    float acc = 0.f;
    for (int k = 0; k < 1024; k++) acc += lmh[k] * W1[k*1024 + n];
    for (int k = 0; k < 1024; k++) acc += rh[k]  * W2[k*1024 + n];
    out[n] = acc;
}

__global__ void gemv_gelu(const float* __restrict__ lmh, const float* __restrict__ W,
                          float* __restrict__ out)
{
    int n = blockIdx.x * 256 + threadIdx.x;
    float acc = 0.f;
    for (int k = 0; k < 1024; k++) acc += lmh[k] * W[k*1024 + n];
    float x = acc;
    float tg = tanhf(0.7978845608028654f * (x + 0.044715f * x*x*x));
    out[n] = 0.5f * x * (1.0f + tg);
}

__global__ void stop_head_k(const float* __restrict__ sp, const float* __restrict__ W,
                            float* __restrict__ out)
{
    __shared__ float r0[256], r1[256];
    int tid = threadIdx.x;
    float a0 = 0.f, a1 = 0.f;
    for (int k = tid; k < 1024; k += 256) {
        float s = sp[k];
        a0 += s * W[2*k];
        a1 += s * W[2*k + 1];
    }
    r0[tid] = a0; r1[tid] = a1; __syncthreads();
    for (int of = 128; of > 0; of >>= 1) {
        if (tid < of) { r0[tid] += r0[tid + of]; r1[tid] += r1[tid + of]; }
        __syncthreads();
    }
    if (tid == 0) out[0] = (r1[0] > r0[0]) ? 1.0f : 0.0f;
}

// ---------------- jax.random.normal(key(42), (1,2,64)), partitionable threefry ----
__device__ __forceinline__ float tf_normal(unsigned bits) {
    float f = __uint_as_float((bits >> 9) | 0x3F800000u) - 1.0f;   // [0,1)
    const float lo = -0.99999994f;        // nextafter(-1, 0)
    float u = f * 2.0f + lo;              // (hi-lo) rounds to 2.0f
    u = fmaxf(lo, u);
    float w = -log1pf(-u * u);            // matches XLA ErfInv32
    float p;
    if (w < 5.0f) {
        w -= 2.5f;
        p = 2.81022636e-08f;
        p = fmaf(p, w, 3.43273939e-07f);
        p = fmaf(p, w, -3.5233877e-06f);
        p = fmaf(p, w, -4.39150654e-06f);
        p = fmaf(p, w, 0.00021858087f);
        p = fmaf(p, w, -0.00125372503f);
        p = fmaf(p, w, -0.00417768164f);
        p = fmaf(p, w, 0.246640727f);
        p = fmaf(p, w, 1.50140941f);
    } else {
        w = sqrtf(w) - 3.0f;
        p = -0.000200214257f;
        p = fmaf(p, w, 0.000100950558f);
        p = fmaf(p, w, 0.00134934322f);
        p = fmaf(p, w, -0.00367342844f);
        p = fmaf(p, w, 0.00573950773f);
        p = fmaf(p, w, -0.0076224613f);
        p = fmaf(p, w, 0.00943887047f);
        p = fmaf(p, w, 1.00167406f);
        p = fmaf(p, w, 2.83297682f);
    }
    return 1.41421356f * (p * u);         // sqrt(2)*erfinv(u)
}

// Partitionable mode (jax_threefry_partitionable=True, default in modern JAX):
// per element i: counter64 = i -> (x0, x1) = (hi32, lo32) = (0, i);
// bits = threefry2x32(key, (x0,x1)); output = bits[0] ^ bits[1].
__global__ void rnd_k(float* out) {
    int i = threadIdx.x;                  // 128 threads
    unsigned x0 = 0u, x1 = (unsigned)i;
    const unsigned K0 = 0u, K1 = 42u, K2 = 0u ^ 42u ^ 0x1BD11BDAu;
    unsigned ks[3] = {K0, K1, K2};
    x0 += K0; x1 += K1;
    const int rot[5][4] = {{13,15,26,6},{17,29,16,24},{13,15,26,6},{17,29,16,24},{13,15,26,6}};
    #pragma unroll
    for (int r = 0; r < 5; r++) {
        #pragma unroll
        for (int j = 0; j < 4; j++) {
            x0 += x1;
            int d = rot[r][j];
            x1 = (x1 << d) | (x1 >> (32 - d));
            x1 ^= x0;
        }
        x0 += ks[(r + 1) % 3];
        x1 += ks[(r + 2) % 3] + (unsigned)(r + 1);
    }
    out[i] = tf_normal(x0 ^ x1);
}

// ---------------- host ----------------
extern "C" void kernel_launch(void* const* d_in, const int* in_sizes, int n_in,
                              void* d_out, int out_size)
{
    const float* hidden = (const float*)d_in[0];
    const float* feat   = (const float*)d_in[1];
    const float* kc     = (const float*)d_in[2];
    const float* vc     = (const float*)d_in[3];
    const float* mf     = (const float*)d_in[4];
    const float* ln1    = (const float*)d_in[5];
    const float* ln2    = (const float*)d_in[6];
    const float* qw     = (const float*)d_in[7];
    const float* kw     = (const float*)d_in[8];
    const float* vw     = (const float*)d_in[9];
    const float* ow     = (const float*)d_in[10];
    const float* gw     = (const float*)d_in[11];
    const float* uw     = (const float*)d_in[12];
    const float* dw     = (const float*)d_in[13];
    const float* bnw    = (const float*)d_in[14];
    const float* rnw    = (const float*)d_in[15];
    const float* fdw    = (const float*)d_in[16];
    const float* fuw    = (const float*)d_in[17];
    const float* ldw    = (const float*)d_in[18];
    const float* rdw    = (const float*)d_in[19];
    const float* spw    = (const float*)d_in[20];
    const float* shw    = (const float*)d_in[21];

    float* out = (float*)d_out;
    float* oK = out;                        // 16*2*64*2048
    float* oV = out + 4194304;              // 16*2*2048*64
    float* oD = out + 8388608;              // 1024
    float* oR = out + 8389632;              // 128
    float* oS = out + 8389760;              // 1

    float *h_, *x_, *q_, *k_, *v_, *gt_, *up_, *sc_, *z_, *f_, *lmh_, *rh_, *sp_, *tc_, *ts_;
    cudaGetSymbolAddress((void**)&h_,   g_h);
    cudaGetSymbolAddress((void**)&x_,   g_x);
    cudaGetSymbolAddress((void**)&q_,   g_q);
    cudaGetSymbolAddress((void**)&k_,   g_k);
    cudaGetSymbolAddress((void**)&v_,   g_v);
    cudaGetSymbolAddress((void**)&gt_,  g_gate);
    cudaGetSymbolAddress((void**)&up_,  g_up);
    cudaGetSymbolAddress((void**)&sc_,  g_scores);
    cudaGetSymbolAddress((void**)&z_,   g_z);
    cudaGetSymbolAddress((void**)&f_,   g_f);
    cudaGetSymbolAddress((void**)&lmh_, g_lmh);
    cudaGetSymbolAddress((void**)&rh_,  g_rh);
    cudaGetSymbolAddress((void**)&sp_,  g_sp);
    cudaGetSymbolAddress((void**)&tc_,  g_cos);
    cudaGetSymbolAddress((void**)&ts_,  g_sin);

    copy_f4<<<1024, 256>>>(h_, hidden, 262144);
    copy_caches<<<4096, 256>>>(kc, vc, oK, oV);
    rope_tab<<<1024, 32>>>(tc_, ts_);

    for (int l = 0; l < LTOT; l++) {
        if (l == 12) {
            rms_rows<<<1024, 256>>>(h_, bnw, x_);
            sgemm<<<dim3(1, 12, 1), 256>>>(x_ + 256*1024, 1024, 0, fdw, 32, 0, 1,
                                           z_, 32, 0, 768, 32, 1024, 0);
            tanh_quant<<<96, 256>>>(z_, 24576);
            sgemm<<<dim3(16, 12, 1), 256>>>(z_, 32, 0, fuw, 1024, 0, 1,
                                            f_, 1024, 0, 768, 1024, 32, 0);
            build_h<<<4096, 256>>>(h_, x_, f_, feat, lmh_);
        }
        const float* qwl = qw + (long)l * 1048576;
        const float* kwl = kw + (long)l * 131072;
        const float* vwl = vw + (long)l * 131072;
        const float* owl = ow + (long)l * 1048576;
        const float* gwl = gw + (long)l * 2621440;
        const float* uwl = uw + (long)l * 2621440;
        const float* dwl = dw + (long)l * 2621440;
        float* lK = oK + (long)l * 262144;   // [2][64][2048]
        float* lV = oV + (long)l * 262144;   // [2][2048][64]

        rms_rows<<<1024, 256>>>(h_, ln1 + l*1024, x_);
        sgemm<<<dim3(16, 16, 1), 256>>>(x_, 1024, 0, qwl, 1024, 0, 1,
                                        q_, 1024, 0, 1024, 1024, 1024, 0);
        sgemm<<<dim3(2, 16, 1), 256>>>(x_, 1024, 0, kwl, 128, 0, 1,
                                       k_, 128, 0, 1024, 128, 1024, 0);
        sgemm<<<dim3(2, 16, 1), 256>>>(x_, 1024, 0, vwl, 128, 0, 1,
                                       v_, 128, 0, 1024, 128, 1024, 0);
        rope_scatter<<<1024, 128>>>(q_, k_, v_, lK, lV, tc_, ts_);
        // scores[h] = Q_h (1024x64) @ Kfull[h/8] (64x2048)
        sgemm<<<dim3(32, 16, 16), 256>>>(q_, 1024, 64, lK, 2048, 131072, 8,
                                         sc_, 2048, 2097152, 1024, 2048, 64, 0);
        softmax_mask<<<16384, 256>>>(sc_, mf);
        // out[h] = P_h (1024x2048) @ Vfull[h/8] (2048x64) -> q_ reused
        sgemm<<<dim3(1, 16, 16), 256>>>(sc_, 2048, 2097152, lV, 64, 131072, 8,
                                        q_, 1024, 64, 1024, 64, 2048, 0);
        sgemm<<<dim3(16, 16, 1), 256>>>(q_, 1024, 0, owl, 1024, 0, 1,
                                        h_, 1024, 0, 1024, 1024, 1024, 1);
        rms_rows<<<1024, 256>>>(h_, ln2 + l*1024, x_);
        sgemm<<<dim3(40, 16, 1), 256>>>(x_, 1024, 0, gwl, 2560, 0, 1,
                                        gt_, 2560, 0, 1024, 2560, 1024, 0);
        sgemm<<<dim3(40, 16, 1), 256>>>(x_, 1024, 0, uwl, 2560, 0, 1,
                                        up_, 2560, 0, 1024, 2560, 1024, 0);
        silu_mul<<<2560, 256>>>(gt_, up_, 655360);
        sgemm<<<dim3(16, 16, 1), 256>>>(gt_, 2560, 0, dwl, 1024, 0, 1,
                                        h_, 1024, 0, 1024, 1024, 2560, 1);
    }

    rms_rows<<<1, 256>>>(h_ + 1023*1024, rnw, rh_);
    gemv_dit<<<4, 256>>>(lmh_, rh_, ldw, rdw, oD);
    gemv_gelu<<<4, 256>>>(lmh_, spw, sp_);
    stop_head_k<<<1, 256>>>(sp_, shw, oS);
    rnd_k<<<1, 128>>>(oR);
}

// round 13
// speedup vs baseline: 1.2924x; 1.2924x over previous
#include <cuda_runtime.h>
#include <cuda_bf16.h>
#include <math.h>
#include <stdint.h>

// ---------------- constants ----------------
#define SEQ    1024
#define DMODEL 1024
#define NHEAD  16
#define NKV    2
#define HDIM   64
#define FFDIM  2560
#define KVLEN  2048
#define LTOT   16
#define RSCALE 0.35355339059327373f   // 64^-0.25

// ---------------- fp32 scratch ----------------
__device__ float g_h[SEQ * DMODEL];
__device__ float g_x[SEQ * DMODEL];
__device__ float g_q[SEQ * DMODEL];            // roped q / attention out
__device__ float g_qkv[SEQ * 1280];            // fused qkv gemm out
__device__ float g_gu[SEQ * 5120];             // fused gate|up gemm out
__device__ float g_gate[SEQ * FFDIM];          // silu(gate)*up
__device__ float g_scores[NHEAD * SEQ * KVLEN];// 134 MB
__device__ float g_z[768 * 32];
__device__ float g_f[768 * DMODEL];
__device__ float g_lmh[DMODEL];
__device__ float g_rh[DMODEL];
__device__ float g_sp[DMODEL];
__device__ float g_cos[SEQ * 32];
__device__ float g_sin[SEQ * 32];

// ---------------- bf16 hi/lo scratch ----------------
// weights: [L][2 planes][N][K]
__device__ __nv_bfloat16 g_wqkv[2L * LTOT * 1280 * 1024];
__device__ __nv_bfloat16 g_wo  [2L * LTOT * 1024 * 1024];
__device__ __nv_bfloat16 g_wgu [2L * LTOT * 5120 * 1024];
__device__ __nv_bfloat16 g_wd  [2L * LTOT * 1024 * 2560];
// activations hi/lo (max 1024x2560)
__device__ __nv_bfloat16 g_ac[2L * 1024 * 2560];
// P (softmax probs) hi/lo
__device__ __nv_bfloat16 g_ps[2L * NHEAD * SEQ * KVLEN];
// per-layer K^T cache bf16: [2 pl][2 kv][2048 s][64 d]
__device__ __nv_bfloat16 g_kb[2L * 2 * 2048 * 64];
// per-layer V^T cache bf16: [2 pl][2 kv][128 d(pad)][2048 s]
__device__ __nv_bfloat16 g_vb[2L * 2 * 128 * 2048];

// ---------------- mma.sync bf16-split GEMM ----------------
// C[M,N] (+)= A[M,K] @ B^T, A hi/lo [M][K] (lo at +aPlane), B hi/lo [N][K].
// 3-product split: Ah*Bh + Ah*Bl + Al*Bh, fp32 accum.
// Block 128x128, BK=32, 256 thr, 8 warps (2m x 4n), warp tile 64x32.
#define MMA16816(d, a, b) \
    asm volatile("mma.sync.aligned.m16n8k16.row.col.f32.bf16.bf16.f32 " \
        "{%0,%1,%2,%3}, {%4,%5,%6,%7}, {%8,%9}, {%0,%1,%2,%3};" \
        : "+f"((d)[0]), "+f"((d)[1]), "+f"((d)[2]), "+f"((d)[3]) \
        : "r"((a)[0]), "r"((a)[1]), "r"((a)[2]), "r"((a)[3]), \
          "r"((b)[0]), "r"((b)[1]))

__global__ __launch_bounds__(256) void mma_gemm(
    const __nv_bfloat16* __restrict__ A, long aPlane, int lda, long zA,
    const __nv_bfloat16* __restrict__ B, long bPlane, int ldb, long zB, int bdiv,
    float* __restrict__ C, int ldc, long zC,
    int K, int nv, int addTo)
{
    __shared__ __nv_bfloat16 sA[2][128][40];
    __shared__ __nv_bfloat16 sB[2][128][40];
    int z = blockIdx.z;
    A += (long)z * zA;
    B += (long)(z / bdiv) * zB;
    C += (long)z * zC;
    int m0 = blockIdx.y << 7, n0 = blockIdx.x << 7;
    int tid = threadIdx.x, lane = tid & 31, wid = tid >> 5;
    int wm = (wid >> 2) << 6, wn = (wid & 3) << 5;
    int g = lane >> 2, t2 = (lane & 3) << 1;
    int lr = tid >> 1, lc = (tid & 1) << 4;

    float acc[4][4][4];
    #pragma unroll
    for (int i = 0; i < 4; i++)
        #pragma unroll
        for (int j = 0; j < 4; j++)
            #pragma unroll
            for (int r = 0; r < 4; r++) acc[i][j][r] = 0.f;

    for (int kb = 0; kb < K; kb += 32) {
        const __nv_bfloat16* Ag = A + (long)(m0 + lr) * lda + kb + lc;
        const __nv_bfloat16* Bg = B + (long)(n0 + lr) * ldb + kb + lc;
        *(uint4*)&sA[0][lr][lc]   = *(const uint4*)Ag;
        *(uint4*)&sA[0][lr][lc+8] = *(const uint4*)(Ag + 8);
        *(uint4*)&sA[1][lr][lc]   = *(const uint4*)(Ag + aPlane);
        *(uint4*)&sA[1][lr][lc+8] = *(const uint4*)(Ag + aPlane + 8);
        *(uint4*)&sB[0][lr][lc]   = *(const uint4*)Bg;
        *(uint4*)&sB[0][lr][lc+8] = *(const uint4*)(Bg + 8);
        *(uint4*)&sB[1][lr][lc]   = *(const uint4*)(Bg + bPlane);
        *(uint4*)&sB[1][lr][lc+8] = *(const uint4*)(Bg + bPlane + 8);
        __syncthreads();
        #pragma unroll
        for (int s = 0; s < 32; s += 16) {
            uint32_t ah[4][4], al[4][4], bh[4][2], bl[4][2];
            #pragma unroll
            for (int i = 0; i < 4; i++) {
                int row = wm + (i << 4) + g;
                ah[i][0] = *(const uint32_t*)&sA[0][row][s+t2];
                ah[i][1] = *(const uint32_t*)&sA[0][row+8][s+t2];
                ah[i][2] = *(const uint32_t*)&sA[0][row][s+t2+8];
                ah[i][3] = *(const uint32_t*)&sA[0][row+8][s+t2+8];
                al[i][0] = *(const uint32_t*)&sA[1][row][s+t2];
                al[i][1] = *(const uint32_t*)&sA[1][row+8][s+t2];
                al[i][2] = *(const uint32_t*)&sA[1][row][s+t2+8];
                al[i][3] = *(const uint32_t*)&sA[1][row+8][s+t2+8];
            }
            #pragma unroll
            for (int j = 0; j < 4; j++) {
                int nr = wn + (j << 3) + g;
                bh[j][0] = *(const uint32_t*)&sB[0][nr][s+t2];
                bh[j][1] = *(const uint32_t*)&sB[0][nr][s+t2+8];
                bl[j][0] = *(const uint32_t*)&sB[1][nr][s+t2];
                bl[j][1] = *(const uint32_t*)&sB[1][nr][s+t2+8];
            }
            #pragma unroll
            for (int i = 0; i < 4; i++)
                #pragma unroll
                for (int j = 0; j < 4; j++) {
                    MMA16816(acc[i][j], ah[i], bh[j]);
                    MMA16816(acc[i][j], ah[i], bl[j]);
                    MMA16816(acc[i][j], al[i], bh[j]);
                }
        }
        __syncthreads();
    }
    #pragma unroll
    for (int i = 0; i < 4; i++) {
        int row = m0 + wm + (i << 4) + g;
        #pragma unroll
        for (int j = 0; j < 4; j++) {
            int col = n0 + wn + (j << 3) + t2;
            if (col < nv) {
                float* p0 = C + (long)row * ldc + col;
                float* p1 = p0 + ((long)ldc << 3);
                if (addTo) {
                    p0[0] += acc[i][j][0]; p0[1] += acc[i][j][1];
                    p1[0] += acc[i][j][2]; p1[1] += acc[i][j][3];
                } else {
                    p0[0] = acc[i][j][0]; p0[1] = acc[i][j][1];
                    p1[0] = acc[i][j][2]; p1[1] = acc[i][j][3];
                }
            }
        }
    }
}

// ---------------- weight convert+transpose: W[K][Nsrc] fp32 -> [n][K] bf16 hi/lo ----
__global__ __launch_bounds__(256) void conv_w(
    const float* __restrict__ W, long wStride,
    __nv_bfloat16* __restrict__ out, long layerStride, long plane, long rowOff,
    int K, int Nsrc)
{
    const float* Wl = W + (long)blockIdx.z * wStride;
    __nv_bfloat16* Ol = out + (long)blockIdx.z * layerStride + rowOff * K;
    int k0 = blockIdx.y << 5, n0 = blockIdx.x << 5;
    __shared__ float t[32][33];
    int tx = threadIdx.x & 31, ty = threadIdx.x >> 5;
    #pragma unroll
    for (int r = 0; r < 4; r++)
        t[ty + (r << 3)][tx] = Wl[(long)(k0 + ty + (r << 3)) * Nsrc + n0 + tx];
    __syncthreads();
    #pragma unroll
    for (int r = 0; r < 4; r++) {
        int n = ty + (r << 3);
        float v = t[tx][n];
        __nv_bfloat16 hi = __float2bfloat16(v);
        long o = (long)(n0 + n) * K + k0 + tx;
        Ol[o] = hi;
        Ol[plane + o] = __float2bfloat16(v - __bfloat162float(hi));
    }
}

// ---------------- fp32 [R][C] -> bf16 hi/lo transposed [C][R] ----------------
__global__ __launch_bounds__(256) void conv_t(
    const float* __restrict__ in, long inZ,
    __nv_bfloat16* __restrict__ out, long outZ, long plane, int R, int C)
{
    __shared__ float t[32][33];
    const float* iz = in + (long)blockIdx.z * inZ;
    __nv_bfloat16* oz = out + (long)blockIdx.z * outZ;
    int r0 = blockIdx.y << 5, c0 = blockIdx.x << 5;
    int tx = threadIdx.x & 31, ty = threadIdx.x >> 5;
    #pragma unroll
    for (int rr = 0; rr < 4; rr++)
        t[ty + (rr << 3)][tx] = iz[(long)(r0 + ty + (rr << 3)) * C + c0 + tx];
    __syncthreads();
    #pragma unroll
    for (int rr = 0; rr < 4; rr++) {
        int c = ty + (rr << 3);
        float v = t[tx][c];
        __nv_bfloat16 hi = __float2bfloat16(v);
        long o = (long)(c0 + c) * R + r0 + tx;
        oz[o] = hi;
        oz[plane + o] = __float2bfloat16(v - __bfloat162float(hi));
    }
}

// ---------------- activation fp32 -> bf16 hi/lo ----------------
__global__ void conv_act(const float* __restrict__ x, __nv_bfloat16* __restrict__ o,
                         long plane, int n)
{
    int i = blockIdx.x * 256 + threadIdx.x;
    if (i >= n) return;
    float v = x[i];
    __nv_bfloat16 hi = __float2bfloat16(v);
    o[i] = hi;
    o[plane + i] = __float2bfloat16(v - __bfloat162float(hi));
}

__global__ void zero_bf(__nv_bfloat16* p, int n) {
    int i = blockIdx.x * 256 + threadIdx.x;
    if (i < n) p[i] = __float2bfloat16(0.f);
}

// ---------------- scalar SGEMM (FSQ only) ----------------
__global__ __launch_bounds__(256) void sgemm(
    const float* __restrict__ A, int lda, long sA,
    const float* __restrict__ B, int ldb, long sB, int bdiv,
    float* __restrict__ C, int ldc, long sC,
    int M, int N, int K, int addTo)
{
    __shared__ float As[16][68];
    __shared__ float Bs[16][68];
    int z = blockIdx.z;
    A += (long)z * sA;
    B += (long)(z / bdiv) * sB;
    C += (long)z * sC;
    int bm = blockIdx.y * 64, bn = blockIdx.x * 64;
    int tid = threadIdx.x;
    int ty = tid >> 4, tx = tid & 15;
    int ar = tid >> 2,  ac = (tid & 3) << 2;
    int br = tid >> 4,  bc = (tid & 15) << 2;

    float acc[4][4] = {};
    for (int k0 = 0; k0 < K; k0 += 16) {
        float4 a4 = *(const float4*)(A + (long)(bm + ar) * lda + (k0 + ac));
        As[ac+0][ar] = a4.x; As[ac+1][ar] = a4.y;
        As[ac+2][ar] = a4.z; As[ac+3][ar] = a4.w;
        float4 b4;
        if (bn + bc < N) b4 = *(const float4*)(B + (long)(k0 + br) * ldb + (bn + bc));
        else             b4 = make_float4(0.f, 0.f, 0.f, 0.f);
        *(float4*)&Bs[br][bc] = b4;
        __syncthreads();
        #pragma unroll
        for (int kk = 0; kk < 16; kk++) {
            float4 av = *(const float4*)&As[kk][ty << 2];
            float4 bv = *(const float4*)&Bs[kk][tx << 2];
            acc[0][0] += av.x * bv.x; acc[0][1] += av.x * bv.y;
            acc[0][2] += av.x * bv.z; acc[0][3] += av.x * bv.w;
            acc[1][0] += av.y * bv.x; acc[1][1] += av.y * bv.y;
            acc[1][2] += av.y * bv.z; acc[1][3] += av.y * bv.w;
            acc[2][0] += av.z * bv.x; acc[2][1] += av.z * bv.y;
            acc[2][2] += av.z * bv.z; acc[2][3] += av.z * bv.w;
            acc[3][0] += av.w * bv.x; acc[3][1] += av.w * bv.y;
            acc[3][2] += av.w * bv.z; acc[3][3] += av.w * bv.w;
        }
        __syncthreads();
    }
    int m0 = bm + (ty << 2), n0 = bn + (tx << 2);
    if (n0 < N) {
        #pragma unroll
        for (int i = 0; i < 4; i++) {
            float* cp = C + (long)(m0 + i) * ldc + n0;
            float4 cv = make_float4(acc[i][0], acc[i][1], acc[i][2], acc[i][3]);
            if (addTo) {
                float4 o = *(const float4*)cp;
                cv.x += o.x; cv.y += o.y; cv.z += o.z; cv.w += o.w;
            }
            *(float4*)cp = cv;
        }
    }
}

// ---------------- RMSNorm ----------------
__global__ __launch_bounds__(256) void rms_rows(
    const float* __restrict__ x, const float* __restrict__ w, float* __restrict__ o)
{
    long r = blockIdx.x;
    const float4* xr = (const float4*)(x + r * DMODEL);
    float4* orow = (float4*)(o + r * DMODEL);
    int tid = threadIdx.x;
    float4 v = xr[tid];
    float ss = v.x*v.x + v.y*v.y + v.z*v.z + v.w*v.w;
    __shared__ float red[256];
    red[tid] = ss; __syncthreads();
    for (int of = 128; of > 0; of >>= 1) {
        if (tid < of) red[tid] += red[tid + of];
        __syncthreads();
    }
    float scale = rsqrtf(red[0] * (1.0f / DMODEL) + 1e-5f);
    float4 ww = ((const float4*)w)[tid];
    orow[tid] = make_float4(v.x*scale*ww.x, v.y*scale*ww.y, v.z*scale*ww.z, v.w*scale*ww.w);
}

// ---------------- RoPE tables ----------------
__global__ void rope_tab(float* gc, float* gs) {
    int t = blockIdx.x, i = threadIdx.x;
    double inv = exp(-(double)i * (9.210340371976184 / 32.0));
    double ang = (double)(1024 + t) * inv;
    gc[t*32 + i] = (float)cos(ang) * RSCALE;
    gs[t*32 + i] = (float)sin(ang) * RSCALE;
}

// ---------------- RoPE apply + scatter (reads fused qkv, ld 1280) ----------------
__global__ __launch_bounds__(128) void rope_scatter(
    const float* __restrict__ qkv, float* __restrict__ qo,
    float* __restrict__ oK, float* __restrict__ oV,
    const float* __restrict__ gc, const float* __restrict__ gs)
{
    int t = blockIdx.x, tid = threadIdx.x;
    #pragma unroll
    for (int p = tid; p < 512; p += 128) {
        int h = p >> 5, i = p & 31;
        float c = gc[t*32 + i], s = gs[t*32 + i];
        int b = t*1280 + h*64 + i;
        float x1 = qkv[b], x2 = qkv[b + 32];
        int ob = t*1024 + h*64 + i;
        qo[ob]      = x1*c - x2*s;
        qo[ob + 32] = x2*c + x1*s;
    }
    if (tid < 64) {
        int kv = tid >> 5, i = tid & 31;
        float c = gc[t*32 + i], s = gs[t*32 + i];
        int b = t*1280 + 1024 + kv*64 + i;
        float x1 = qkv[b], x2 = qkv[b + 32];
        oK[(long)(kv*64 + i     ) * KVLEN + 1024 + t] = x1*c - x2*s;
        oK[(long)(kv*64 + i + 32) * KVLEN + 1024 + t] = x2*c + x1*s;
    }
    {
        int kv = tid >> 6, d = tid & 63;
        oV[(long)(kv*KVLEN + 1024 + t) * 64 + d] = qkv[t*1280 + 1152 + tid];
    }
}

// ---------------- softmax ----------------
__global__ __launch_bounds__(256) void softmax_mask(float* __restrict__ S,
                                                    const float* __restrict__ mf)
{
    long r = blockIdx.x;
    int t = (int)(r & 1023);
    float flag = mf[0];
    float* row = S + r * KVLEN;
    int tid = threadIdx.x;
    float vals[8];
    float mx = -1e30f;
    #pragma unroll
    for (int j = 0; j < 8; j++) {
        int s = tid + j*256;
        float m = (s > t) ? (-128.0f * flag) : 0.0f;
        vals[j] = row[s] + m;
        mx = fmaxf(mx, vals[j]);
    }
    __shared__ float red[256];
    red[tid] = mx; __syncthreads();
    for (int of = 128; of > 0; of >>= 1) {
        if (tid < of) red[tid] = fmaxf(red[tid], red[tid + of]);
        __syncthreads();
    }
    mx = red[0]; __syncthreads();
    float sum = 0.f;
    #pragma unroll
    for (int j = 0; j < 8; j++) { vals[j] = expf(vals[j] - mx); sum += vals[j]; }
    red[tid] = sum; __syncthreads();
    for (int of = 128; of > 0; of >>= 1) {
        if (tid < of) red[tid] += red[tid + of];
        __syncthreads();
    }
    float inv = 1.0f / red[0];
    #pragma unroll
    for (int j = 0; j < 8; j++) row[tid + j*256] = vals[j] * inv;
}

// ---------------- elementwise ----------------
// fused [1024][5120] gate|up -> out [1024][2560]
__global__ void silu_mul(const float* __restrict__ gu, float* __restrict__ o, int n4) {
    int i = blockIdx.x * blockDim.x + threadIdx.x;
    if (i >= n4) return;                 // n4 = 1024*640
    int t = i / 640, c4 = i - t * 640;
    float4 a = ((const float4*)gu)[(long)t * 1280 + c4];
    float4 b = ((const float4*)gu)[(long)t * 1280 + 640 + c4];
    a.x = a.x / (1.f + expf(-a.x)) * b.x;
    a.y = a.y / (1.f + expf(-a.y)) * b.y;
    a.z = a.z / (1.f + expf(-a.z)) * b.z;
    a.w = a.w / (1.f + expf(-a.w)) * b.w;
    ((float4*)o)[i] = a;
}

__global__ void tanh_quant(float* z, int n) {
    int i = blockIdx.x * blockDim.x + threadIdx.x;
    if (i >= n) return;
    float t = tanhf(z[i]);
    float r = rintf(t * 4.0f) * 0.25f;
    z[i] = t + (r - t);
}

__global__ void copy_f4(float* __restrict__ dst, const float* __restrict__ src, int n4) {
    int i = blockIdx.x * blockDim.x + threadIdx.x;
    if (i < n4) ((float4*)dst)[i] = ((const float4*)src)[i];
}

__global__ void build_h(float* __restrict__ h, const float* __restrict__ x,
                        const float* __restrict__ f, const float* __restrict__ feat,
                        float* __restrict__ lmh)
{
    int i = blockIdx.x * 256 + threadIdx.x;
    int row = i >> 10, col = i & 1023;
    if (row < 256) h[i] = x[i];
    else {
        int j = ((row - 256) << 10) + col;
        h[i] = f[j] + feat[j];
    }
    if (row == 1023) lmh[col] = f[(767 << 10) + col];
}

__global__ void copy_caches(const float* __restrict__ kc, const float* __restrict__ vc,
                            float* __restrict__ oK, float* __restrict__ oV)
{
    int i = blockIdx.x * 256 + threadIdx.x;
    if (i < 524288) {
        int row = i >> 8, c4 = i & 255;
        ((float4*)oK)[(long)row * 512 + c4] = ((const float4*)kc)[i];
    } else {
        int j = i - 524288;
        int pair = j >> 14, off = j & 16383;
        ((float4*)oV)[(long)pair * 32768 + off] = ((const float4*)vc)[j];
    }
}

// ---------------- small heads ----------------
__global__ void gemv_dit(const float* __restrict__ lmh, const float* __restrict__ rh,
                         const float* __restrict__ W1, const float* __restrict__ W2,
                         float* __restrict__ out)
{
    int n = blockIdx.x * 256 + threadIdx.x;
    float acc = 0.f;
    for (int k = 0; k < 1024; k++) acc += lmh[k] * W1[k*1024 + n];
    for (int k = 0; k < 1024; k++) acc += rh[k]  * W2[k*1024 + n];
    out[n] = acc;
}

__global__ void gemv_gelu(const float* __restrict__ lmh, const float* __restrict__ W,
                          float* __restrict__ out)
{
    int n = blockIdx.x * 256 + threadIdx.x;
    float acc = 0.f;
    for (int k = 0; k < 1024; k++) acc += lmh[k] * W[k*1024 + n];
    float x = acc;
    float tg = tanhf(0.7978845608028654f * (x + 0.044715f * x*x*x));
    out[n] = 0.5f * x * (1.0f + tg);
}

__global__ void stop_head_k(const float* __restrict__ sp, const float* __restrict__ W,
                            float* __restrict__ out)
{
    __shared__ float r0[256], r1[256];
    int tid = threadIdx.x;
    float a0 = 0.f, a1 = 0.f;
    for (int k = tid; k < 1024; k += 256) {
        float s = sp[k];
        a0 += s * W[2*k];
        a1 += s * W[2*k + 1];
    }
    r0[tid] = a0; r1[tid] = a1; __syncthreads();
    for (int of = 128; of > 0; of >>= 1) {
        if (tid < of) { r0[tid] += r0[tid + of]; r1[tid] += r1[tid + of]; }
        __syncthreads();
    }
    if (tid == 0) out[0] = (r1[0] > r0[0]) ? 1.0f : 0.0f;
}

// ---------------- jax.random.normal(key(42)), partitionable threefry ----------------
__device__ __forceinline__ float tf_normal(unsigned bits) {
    float f = __uint_as_float((bits >> 9) | 0x3F800000u) - 1.0f;
    const float lo = -0.99999994f;
    float u = f * 2.0f + lo;
    u = fmaxf(lo, u);
    float w = -log1pf(-u * u);
    float p;
    if (w < 5.0f) {
        w -= 2.5f;
        p = 2.81022636e-08f;
        p = fmaf(p, w, 3.43273939e-07f);
        p = fmaf(p, w, -3.5233877e-06f);
        p = fmaf(p, w, -4.39150654e-06f);
        p = fmaf(p, w, 0.00021858087f);
        p = fmaf(p, w, -0.00125372503f);
        p = fmaf(p, w, -0.00417768164f);
        p = fmaf(p, w, 0.246640727f);
        p = fmaf(p, w, 1.50140941f);
    } else {
        w = sqrtf(w) - 3.0f;
        p = -0.000200214257f;
        p = fmaf(p, w, 0.000100950558f);
        p = fmaf(p, w, 0.00134934322f);
        p = fmaf(p, w, -0.00367342844f);
        p = fmaf(p, w, 0.00573950773f);
        p = fmaf(p, w, -0.0076224613f);
        p = fmaf(p, w, 0.00943887047f);
        p = fmaf(p, w, 1.00167406f);
        p = fmaf(p, w, 2.83297682f);
    }
    return 1.41421356f * (p * u);
}

__global__ void rnd_k(float* out) {
    int i = threadIdx.x;
    unsigned x0 = 0u, x1 = (unsigned)i;
    const unsigned K0 = 0u, K1 = 42u, K2 = 0u ^ 42u ^ 0x1BD11BDAu;
    unsigned ks[3] = {K0, K1, K2};
    x0 += K0; x1 += K1;
    const int rot[5][4] = {{13,15,26,6},{17,29,16,24},{13,15,26,6},{17,29,16,24},{13,15,26,6}};
    #pragma unroll
    for (int r = 0; r < 5; r++) {
        #pragma unroll
        for (int j = 0; j < 4; j++) {
            x0 += x1;
            int d = rot[r][j];
            x1 = (x1 << d) | (x1 >> (32 - d));
            x1 ^= x0;
        }
        x0 += ks[(r + 1) % 3];
        x1 += ks[(r + 2) % 3] + (unsigned)(r + 1);
    }
    out[i] = tf_normal(x0 ^ x1);
}

// ---------------- host ----------------
extern "C" void kernel_launch(void* const* d_in, const int* in_sizes, int n_in,
                              void* d_out, int out_size)
{
    const float* hidden = (const float*)d_in[0];
    const float* feat   = (const float*)d_in[1];
    const float* kc     = (const float*)d_in[2];
    const float* vc     = (const float*)d_in[3];
    const float* mf     = (const float*)d_in[4];
    const float* ln1    = (const float*)d_in[5];
    const float* ln2    = (const float*)d_in[6];
    const float* qw     = (const float*)d_in[7];
    const float* kw     = (const float*)d_in[8];
    const float* vw     = (const float*)d_in[9];
    const float* ow     = (const float*)d_in[10];
    const float* gw     = (const float*)d_in[11];
    const float* uw     = (const float*)d_in[12];
    const float* dw     = (const float*)d_in[13];
    const float* bnw    = (const float*)d_in[14];
    const float* rnw    = (const float*)d_in[15];
    const float* fdw    = (const float*)d_in[16];
    const float* fuw    = (const float*)d_in[17];
    const float* ldw    = (const float*)d_in[18];
    const float* rdw    = (const float*)d_in[19];
    const float* spw    = (const float*)d_in[20];
    const float* shw    = (const float*)d_in[21];

    float* out = (float*)d_out;
    float* oK = out;
    float* oV = out + 4194304;
    float* oD = out + 8388608;
    float* oR = out + 8389632;
    float* oS = out + 8389760;

    float *h_, *x_, *q_, *qkv_, *gu_, *gt_, *sc_, *z_, *f_, *lmh_, *rh_, *sp_, *tc_, *ts_;
    cudaGetSymbolAddress((void**)&h_,   g_h);
    cudaGetSymbolAddress((void**)&x_,   g_x);
    cudaGetSymbolAddress((void**)&q_,   g_q);
    cudaGetSymbolAddress((void**)&qkv_, g_qkv);
    cudaGetSymbolAddress((void**)&gu_,  g_gu);
    cudaGetSymbolAddress((void**)&gt_,  g_gate);
    cudaGetSymbolAddress((void**)&sc_,  g_scores);
    cudaGetSymbolAddress((void**)&z_,   g_z);
    cudaGetSymbolAddress((void**)&f_,   g_f);
    cudaGetSymbolAddress((void**)&lmh_, g_lmh);
    cudaGetSymbolAddress((void**)&rh_,  g_rh);
    cudaGetSymbolAddress((void**)&sp_,  g_sp);
    cudaGetSymbolAddress((void**)&tc_,  g_cos);
    cudaGetSymbolAddress((void**)&ts_,  g_sin);

    __nv_bfloat16 *wqkv_, *wo_, *wgu_, *wd_, *ac_, *ps_, *kb_, *vb_;
    cudaGetSymbolAddress((void**)&wqkv_, g_wqkv);
    cudaGetSymbolAddress((void**)&wo_,   g_wo);
    cudaGetSymbolAddress((void**)&wgu_,  g_wgu);
    cudaGetSymbolAddress((void**)&wd_,   g_wd);
    cudaGetSymbolAddress((void**)&ac_,   g_ac);
    cudaGetSymbolAddress((void**)&ps_,   g_ps);
    cudaGetSymbolAddress((void**)&kb_,   g_kb);
    cudaGetSymbolAddress((void**)&vb_,   g_vb);

    copy_f4<<<1024, 256>>>(h_, hidden, 262144);
    copy_caches<<<4096, 256>>>(kc, vc, oK, oV);
    rope_tab<<<1024, 32>>>(tc_, ts_);
    zero_bf<<<4096, 256>>>(vb_, 1048576);   // zero V^T incl. d-pad rows

    // one-time weight conversion
    const long QKV_PL = 1280L * 1024, O_PL = 1048576L, GU_PL = 5120L * 1024, D_PL = 2621440L;
    conv_w<<<dim3(32, 32, 16), 256>>>(qw, 1048576, wqkv_, 2*QKV_PL, QKV_PL, 0,    1024, 1024);
    conv_w<<<dim3(4,  32, 16), 256>>>(kw, 131072,  wqkv_, 2*QKV_PL, QKV_PL, 1024, 1024, 128);
    conv_w<<<dim3(4,  32, 16), 256>>>(vw, 131072,  wqkv_, 2*QKV_PL, QKV_PL, 1152, 1024, 128);
    conv_w<<<dim3(32, 32, 16), 256>>>(ow, 1048576, wo_,   2*O_PL,   O_PL,   0,    1024, 1024);
    conv_w<<<dim3(80, 32, 16), 256>>>(gw, 2621440, wgu_,  2*GU_PL,  GU_PL,  0,    1024, 2560);
    conv_w<<<dim3(80, 32, 16), 256>>>(uw, 2621440, wgu_,  2*GU_PL,  GU_PL,  2560, 1024, 2560);
    conv_w<<<dim3(32, 80, 16), 256>>>(dw, 2621440, wd_,   2*D_PL,   D_PL,   0,    2560, 1024);

    const long PL_D  = 1048576;   // act plane 1024*1024
    const long PL_FF = 2621440;   // act plane 1024*2560
    const long PL_P  = 33554432;  // P plane 16*1024*2048

    for (int l = 0; l < LTOT; l++) {
        if (l == 12) {
            rms_rows<<<1024, 256>>>(h_, bnw, x_);
            sgemm<<<dim3(1, 12, 1), 256>>>(x_ + 256*1024, 1024, 0, fdw, 32, 0, 1,
                                           z_, 32, 0, 768, 32, 1024, 0);
            tanh_quant<<<96, 256>>>(z_, 24576);
            sgemm<<<dim3(16, 12, 1), 256>>>(z_, 32, 0, fuw, 1024, 0, 1,
                                            f_, 1024, 0, 768, 1024, 32, 0);
            build_h<<<4096, 256>>>(h_, x_, f_, feat, lmh_);
        }
        float* lK = oK + (long)l * 262144;   // [2][64][2048] fp32
        float* lV = oV + (long)l * 262144;   // [2][2048][64] fp32

        rms_rows<<<1024, 256>>>(h_, ln1 + l*1024, x_);
        conv_act<<<4096, 256>>>(x_, ac_, PL_D, 1048576);
        // fused qkv: C [1024][1280]
        mma_gemm<<<dim3(10, 8, 1), 256>>>(ac_, PL_D, 1024, 0,
            wqkv_ + (long)l*2*QKV_PL, QKV_PL, 1024, 0, 1,
            qkv_, 1280, 0, 1024, 1280, 0);
        rope_scatter<<<1024, 128>>>(qkv_, q_, lK, lV, tc_, ts_);
        // K^T: [2][64][2048] -> [2][2048][64] bf16 hi/lo
        conv_t<<<dim3(64, 2, 2), 256>>>(lK, 131072, kb_, 131072, 262144, 64, 2048);
        // V^T: [2][2048][64] -> [2][128pad][2048] bf16 hi/lo
        conv_t<<<dim3(2, 64, 2), 256>>>(lV, 131072, vb_, 262144, 524288, 2048, 64);
        conv_act<<<4096, 256>>>(q_, ac_, PL_D, 1048576);
        // scores[h] = Q_h [1024x64] @ K_kv^T, C [1024][2048]
        mma_gemm<<<dim3(16, 8, 16), 256>>>(ac_, PL_D, 1024, 64,
            kb_, 262144, 64, 131072, 8,
            sc_, 2048, 2097152, 64, 2048, 0);
        softmax_mask<<<16384, 256>>>(sc_, mf);
        conv_act<<<131072, 256>>>(sc_, ps_, PL_P, 33554432);
        // out[h] = P_h [1024x2048] @ V_kv, C cols h*64..h*64+63
        mma_gemm<<<dim3(1, 8, 16), 256>>>(ps_, PL_P, 2048, 2097152,
            vb_, 524288, 2048, 262144, 8,
            q_, 1024, 64, 2048, 64, 0);
        conv_act<<<4096, 256>>>(q_, ac_, PL_D, 1048576);
        mma_gemm<<<dim3(8, 8, 1), 256>>>(ac_, PL_D, 1024, 0,
            wo_ + (long)l*2*O_PL, O_PL, 1024, 0, 1,
            h_, 1024, 0, 1024, 1024, 1);
        rms_rows<<<1024, 256>>>(h_, ln2 + l*1024, x_);
        conv_act<<<4096, 256>>>(x_, ac_, PL_D, 1048576);
        // fused gate|up: C [1024][5120]
        mma_gemm<<<dim3(40, 8, 1), 256>>>(ac_, PL_D, 1024, 0,
            wgu_ + (long)l*2*GU_PL, GU_PL, 1024, 0, 1,
            gu_, 5120, 0, 1024, 5120, 0);
        silu_mul<<<2560, 256>>>(gu_, gt_, 655360);
        conv_act<<<10240, 256>>>(gt_, ac_, PL_FF, 2621440);
        mma_gemm<<<dim3(8, 8, 1), 256>>>(ac_, PL_FF, 2560, 0,
            wd_ + (long)l*2*D_PL, D_PL, 2560, 0, 1,
            h_, 1024, 0, 2560, 1024, 1);
    }

    rms_rows<<<1, 256>>>(h_ + 1023*1024, rnw, rh_);
    gemv_dit<<<4, 256>>>(lmh_, rh_, ldw, rdw, oD);
    gemv_gelu<<<4, 256>>>(lmh_, spw, sp_);
    stop_head_k<<<1, 256>>>(sp_, shw, oS);
    rnd_k<<<1, 128>>>(oR);
}

// round 14
// speedup vs baseline: 1.6023x; 1.2398x over previous
#include <cuda_runtime.h>
#include <cuda_bf16.h>
#include <math.h>
#include <stdint.h>

// ---------------- constants ----------------
#define SEQ    1024
#define DMODEL 1024
#define NHEAD  16
#define NKV    2
#define HDIM   64
#define FFDIM  2560
#define KVLEN  2048
#define LTOT   16
#define RSCALE 0.35355339059327373f   // 64^-0.25

// ---------------- fp32 scratch ----------------
__device__ float g_h[SEQ * DMODEL];
__device__ float g_x[SEQ * DMODEL];
__device__ float g_q[SEQ * DMODEL];            // attention out (fp32)
__device__ float g_qkv[SEQ * 1280];            // fused qkv gemm out
__device__ float g_gu[SEQ * 5120];             // fused gate|up gemm out
__device__ float g_scores[NHEAD * SEQ * KVLEN];// 134 MB
__device__ float g_z[768 * 32];
__device__ float g_f[768 * DMODEL];
__device__ float g_lmh[DMODEL];
__device__ float g_rh[DMODEL];
__device__ float g_sp[DMODEL];
__device__ float g_cos[SEQ * 32];
__device__ float g_sin[SEQ * 32];

// ---------------- bf16 hi/lo scratch ----------------
__device__ __nv_bfloat16 g_wqkv[2L * LTOT * 1280 * 1024];
__device__ __nv_bfloat16 g_wo  [2L * LTOT * 1024 * 1024];
__device__ __nv_bfloat16 g_wgu [2L * LTOT * 5120 * 1024];
__device__ __nv_bfloat16 g_wd  [2L * LTOT * 1024 * 2560];
__device__ __nv_bfloat16 g_ac[2L * 1024 * 2560];            // activation hi/lo
__device__ __nv_bfloat16 g_ps[2L * NHEAD * SEQ * KVLEN];    // P hi/lo
// all-layer K cache bf16: [L][2 pl][2 kv][2048 s][64 d]
__device__ __nv_bfloat16 g_kb[(long)LTOT * 2 * 2 * 2048 * 64];
// all-layer V cache bf16: [L][2 pl][2 kv][128 dpad][2048 s]
__device__ __nv_bfloat16 g_vb[(long)LTOT * 2 * 2 * 128 * 2048];

// ---------------- asm helpers ----------------
#define MMA16816(d, a, b) \
    asm volatile("mma.sync.aligned.m16n8k16.row.col.f32.bf16.bf16.f32 " \
        "{%0,%1,%2,%3}, {%4,%5,%6,%7}, {%8,%9}, {%0,%1,%2,%3};" \
        : "+f"((d)[0]), "+f"((d)[1]), "+f"((d)[2]), "+f"((d)[3]) \
        : "r"((a)[0]), "r"((a)[1]), "r"((a)[2]), "r"((a)[3]), \
          "r"((b)[0]), "r"((b)[1]))

#define LDSM4(r0, r1, r2, r3, addr) \
    asm volatile("ldmatrix.sync.aligned.m8n8.x4.shared.b16 {%0,%1,%2,%3}, [%4];" \
        : "=r"(r0), "=r"(r1), "=r"(r2), "=r"(r3) : "r"(addr))

#define CP_ASYNC16(dst, src) \
    asm volatile("cp.async.cg.shared.global [%0], [%1], 16;" :: "r"(dst), "l"(src))
#define CP_COMMIT asm volatile("cp.async.commit_group;")
#define CP_WAIT0  asm volatile("cp.async.wait_group 0;")
#define CP_WAIT1  asm volatile("cp.async.wait_group 1;")

__device__ __forceinline__ uint32_t smem_u32(const void* p) {
    uint32_t a;
    asm("{ .reg .u64 t; cvta.to.shared.u64 t, %1; cvt.u32.u64 %0, t; }" : "=r"(a) : "l"(p));
    return a;
}

// ---------------- mma.sync bf16-split GEMM, cp.async double-buffered ----------------
// C[M,N] (+)= A[M,K] @ B^T; A hi/lo [M][K] (+aPlane), B hi/lo [N][K] (+bPlane).
// 3-product split: Ah*Bh + Ah*Bl + Al*Bh, fp32 accum.
// Block 128x128, BK=32, 256 thr, 8 warps (2m x 4n), warp tile 64x32.
// dyn smem: 2 buffers x [Ahi|Alo|Bhi|Blo] x 128x40 bf16 = 81920 B.
#define MG_SMEM 81920

__global__ __launch_bounds__(256) void mma_gemm(
    const __nv_bfloat16* __restrict__ A, long aPlane, int lda, long zA,
    const __nv_bfloat16* __restrict__ B, long bPlane, int ldb, long zB, int bdiv,
    float* __restrict__ C, int ldc, long zC,
    int K, int nv, int addTo)
{
    extern __shared__ char smem[];
    uint32_t sb = smem_u32(smem);
    int z = blockIdx.z;
    A += (long)z * zA;
    B += (long)(z / bdiv) * zB;
    C += (long)z * zC;
    int m0 = blockIdx.y << 7, n0 = blockIdx.x << 7;
    int tid = threadIdx.x, lane = tid & 31, wid = tid >> 5;
    int wm = (wid >> 2) << 6, wn = (wid & 3) << 5;
    int t2 = (lane & 3) << 1, g = lane >> 2;
    int lr = tid >> 1, lc = (tid & 1) << 4;            // loader: row, k-elem off
    uint32_t st_off = (uint32_t)(lr * 80 + (lc << 1)); // bytes within plane
    // ldmatrix lane offset: q=lane>>3 selects (row+8, col+8)
    uint32_t lane_off = (uint32_t)(((lane & 7) + (((lane >> 3) & 1) << 3)) * 80
                                   + ((lane >> 4) << 4));

    float acc[4][4][4];
    #pragma unroll
    for (int i = 0; i < 4; i++)
        #pragma unroll
        for (int j = 0; j < 4; j++)
            #pragma unroll
            for (int r = 0; r < 4; r++) acc[i][j][r] = 0.f;

    auto issue_load = [&](int kcc, int buf) {
        const __nv_bfloat16* Asrc = A + (long)(m0 + lr) * lda + (kcc << 5) + lc;
        const __nv_bfloat16* Bsrc = B + (long)(n0 + lr) * ldb + (kcc << 5) + lc;
        uint32_t d = sb + buf * 40960 + st_off;
        CP_ASYNC16(d,         Asrc);
        CP_ASYNC16(d + 16,    Asrc + 8);
        CP_ASYNC16(d + 10240, Asrc + aPlane);
        CP_ASYNC16(d + 10256, Asrc + aPlane + 8);
        CP_ASYNC16(d + 20480, Bsrc);
        CP_ASYNC16(d + 20496, Bsrc + 8);
        CP_ASYNC16(d + 30720, Bsrc + bPlane);
        CP_ASYNC16(d + 30736, Bsrc + bPlane + 8);
    };

    int nch = K >> 5;
    issue_load(0, 0);
    CP_COMMIT;
    for (int kc = 0; kc < nch; kc++) {
        int buf = kc & 1;
        if (kc + 1 < nch) { issue_load(kc + 1, buf ^ 1); CP_COMMIT; CP_WAIT1; }
        else              { CP_WAIT0; }
        __syncthreads();
        uint32_t bb = sb + buf * 40960;
        #pragma unroll
        for (int s = 0; s < 32; s += 16) {
            uint32_t ah[4][4], al[4][4], bh[4][2], bl[4][2];
            #pragma unroll
            for (int i = 0; i < 4; i++) {
                uint32_t ad = bb + (uint32_t)((wm + (i << 4)) * 80 + (s << 1)) + lane_off;
                LDSM4(ah[i][0], ah[i][1], ah[i][2], ah[i][3], ad);
                LDSM4(al[i][0], al[i][1], al[i][2], al[i][3], ad + 10240);
            }
            #pragma unroll
            for (int jp = 0; jp < 2; jp++) {
                uint32_t bd = bb + 20480u + (uint32_t)((wn + (jp << 4)) * 80 + (s << 1)) + lane_off;
                LDSM4(bh[2*jp][0], bh[2*jp+1][0], bh[2*jp][1], bh[2*jp+1][1], bd);
                LDSM4(bl[2*jp][0], bl[2*jp+1][0], bl[2*jp][1], bl[2*jp+1][1], bd + 10240);
            }
            #pragma unroll
            for (int i = 0; i < 4; i++)
                #pragma unroll
                for (int j = 0; j < 4; j++) {
                    MMA16816(acc[i][j], ah[i], bh[j]);
                    MMA16816(acc[i][j], ah[i], bl[j]);
                    MMA16816(acc[i][j], al[i], bh[j]);
                }
        }
        __syncthreads();
    }
    #pragma unroll
    for (int i = 0; i < 4; i++) {
        int row = m0 + wm + (i << 4) + g;
        #pragma unroll
        for (int j = 0; j < 4; j++) {
            int col = n0 + wn + (j << 3) + t2;
            if (col < nv) {
                float* p0 = C + (long)row * ldc + col;
                float* p1 = p0 + ((long)ldc << 3);
                if (addTo) {
                    p0[0] += acc[i][j][0]; p0[1] += acc[i][j][1];
                    p1[0] += acc[i][j][2]; p1[1] += acc[i][j][3];
                } else {
                    p0[0] = acc[i][j][0]; p0[1] = acc[i][j][1];
                    p1[0] = acc[i][j][2]; p1[1] = acc[i][j][3];
                }
            }
        }
    }
}

// ---------------- weight convert+transpose: W[K][Nsrc] fp32 -> [n][K] bf16 hi/lo ----
__global__ __launch_bounds__(256) void conv_w(
    const float* __restrict__ W, long wStride,
    __nv_bfloat16* __restrict__ out, long layerStride, long plane, long rowOff,
    int K, int Nsrc)
{
    const float* Wl = W + (long)blockIdx.z * wStride;
    __nv_bfloat16* Ol = out + (long)blockIdx.z * layerStride + rowOff * K;
    int k0 = blockIdx.y << 5, n0 = blockIdx.x << 5;
    __shared__ float t[32][33];
    int tx = threadIdx.x & 31, ty = threadIdx.x >> 5;
    #pragma unroll
    for (int r = 0; r < 4; r++)
        t[ty + (r << 3)][tx] = Wl[(long)(k0 + ty + (r << 3)) * Nsrc + n0 + tx];
    __syncthreads();
    #pragma unroll
    for (int r = 0; r < 4; r++) {
        int n = ty + (r << 3);
        float v = t[tx][n];
        __nv_bfloat16 hi = __float2bfloat16(v);
        long o = (long)(n0 + n) * K + k0 + tx;
        Ol[o] = hi;
        Ol[plane + o] = __float2bfloat16(v - __bfloat162float(hi));
    }
}

// ---------------- fp32 [R][C] -> bf16 hi/lo transposed [C][R], out ld param ----------
__global__ __launch_bounds__(256) void conv_t(
    const float* __restrict__ in, long inZ,
    __nv_bfloat16* __restrict__ out, long outZ, long plane, int R, int C, int outLd)
{
    __shared__ float t[32][33];
    const float* iz = in + (long)blockIdx.z * inZ;
    __nv_bfloat16* oz = out + (long)blockIdx.z * outZ;
    int r0 = blockIdx.y << 5, c0 = blockIdx.x << 5;
    int tx = threadIdx.x & 31, ty = threadIdx.x >> 5;
    #pragma unroll
    for (int rr = 0; rr < 4; rr++)
        t[ty + (rr << 3)][tx] = iz[(long)(r0 + ty + (rr << 3)) * C + c0 + tx];
    __syncthreads();
    #pragma unroll
    for (int rr = 0; rr < 4; rr++) {
        int c = ty + (rr << 3);
        float v = t[tx][c];
        __nv_bfloat16 hi = __float2bfloat16(v);
        long o = (long)(c0 + c) * outLd + r0 + tx;
        oz[o] = hi;
        oz[plane + o] = __float2bfloat16(v - __bfloat162float(hi));
    }
}

// ---------------- activation fp32 -> bf16 hi/lo ----------------
__global__ void conv_act(const float* __restrict__ x, __nv_bfloat16* __restrict__ o,
                         long plane, int n)
{
    int i = blockIdx.x * 256 + threadIdx.x;
    if (i >= n) return;
    float v = x[i];
    __nv_bfloat16 hi = __float2bfloat16(v);
    o[i] = hi;
    o[plane + i] = __float2bfloat16(v - __bfloat162float(hi));
}

__global__ void zero_bf(__nv_bfloat16* p, int n) {
    int i = blockIdx.x * 256 + threadIdx.x;
    if (i < n) p[i] = __float2bfloat16(0.f);
}

// ---------------- scalar SGEMM (FSQ only) ----------------
__global__ __launch_bounds__(256) void sgemm(
    const float* __restrict__ A, int lda, long sA,
    const float* __restrict__ B, int ldb, long sB, int bdiv,
    float* __restrict__ C, int ldc, long sC,
    int M, int N, int K, int addTo)
{
    __shared__ float As[16][68];
    __shared__ float Bs[16][68];
    int z = blockIdx.z;
    A += (long)z * sA;
    B += (long)(z / bdiv) * sB;
    C += (long)z * sC;
    int bm = blockIdx.y * 64, bn = blockIdx.x * 64;
    int tid = threadIdx.x;
    int ty = tid >> 4, tx = tid & 15;
    int ar = tid >> 2,  ac = (tid & 3) << 2;
    int br = tid >> 4,  bc = (tid & 15) << 2;

    float acc[4][4] = {};
    for (int k0 = 0; k0 < K; k0 += 16) {
        float4 a4 = *(const float4*)(A + (long)(bm + ar) * lda + (k0 + ac));
        As[ac+0][ar] = a4.x; As[ac+1][ar] = a4.y;
        As[ac+2][ar] = a4.z; As[ac+3][ar] = a4.w;
        float4 b4;
        if (bn + bc < N) b4 = *(const float4*)(B + (long)(k0 + br) * ldb + (bn + bc));
        else             b4 = make_float4(0.f, 0.f, 0.f, 0.f);
        *(float4*)&Bs[br][bc] = b4;
        __syncthreads();
        #pragma unroll
        for (int kk = 0; kk < 16; kk++) {
            float4 av = *(const float4*)&As[kk][ty << 2];
            float4 bv = *(const float4*)&Bs[kk][tx << 2];
            acc[0][0] += av.x * bv.x; acc[0][1] += av.x * bv.y;
            acc[0][2] += av.x * bv.z; acc[0][3] += av.x * bv.w;
            acc[1][0] += av.y * bv.x; acc[1][1] += av.y * bv.y;
            acc[1][2] += av.y * bv.z; acc[1][3] += av.y * bv.w;
            acc[2][0] += av.z * bv.x; acc[2][1] += av.z * bv.y;
            acc[2][2] += av.z * bv.z; acc[2][3] += av.z * bv.w;
            acc[3][0] += av.w * bv.x; acc[3][1] += av.w * bv.y;
            acc[3][2] += av.w * bv.z; acc[3][3] += av.w * bv.w;
        }
        __syncthreads();
    }
    int m0 = bm + (ty << 2), n0 = bn + (tx << 2);
    if (n0 < N) {
        #pragma unroll
        for (int i = 0; i < 4; i++) {
            float* cp = C + (long)(m0 + i) * ldc + n0;
            float4 cv = make_float4(acc[i][0], acc[i][1], acc[i][2], acc[i][3]);
            if (addTo) {
                float4 o = *(const float4*)cp;
                cv.x += o.x; cv.y += o.y; cv.z += o.z; cv.w += o.w;
            }
            *(float4*)cp = cv;
        }
    }
}

// ---------------- RMSNorm -> fp32 ----------------
__global__ __launch_bounds__(256) void rms_rows(
    const float* __restrict__ x, const float* __restrict__ w, float* __restrict__ o)
{
    long r = blockIdx.x;
    const float4* xr = (const float4*)(x + r * DMODEL);
    float4* orow = (float4*)(o + r * DMODEL);
    int tid = threadIdx.x;
    float4 v = xr[tid];
    float ss = v.x*v.x + v.y*v.y + v.z*v.z + v.w*v.w;
    __shared__ float red[256];
    red[tid] = ss; __syncthreads();
    for (int of = 128; of > 0; of >>= 1) {
        if (tid < of) red[tid] += red[tid + of];
        __syncthreads();
    }
    float scale = rsqrtf(red[0] * (1.0f / DMODEL) + 1e-5f);
    float4 ww = ((const float4*)w)[tid];
    orow[tid] = make_float4(v.x*scale*ww.x, v.y*scale*ww.y, v.z*scale*ww.z, v.w*scale*ww.w);
}

// ---------------- RMSNorm -> bf16 hi/lo planes ----------------
__global__ __launch_bounds__(256) void rms_bf(
    const float* __restrict__ x, const float* __restrict__ w,
    __nv_bfloat16* __restrict__ o, long plane)
{
    long r = blockIdx.x;
    const float4* xr = (const float4*)(x + r * DMODEL);
    int tid = threadIdx.x;
    float4 v = xr[tid];
    float ss = v.x*v.x + v.y*v.y + v.z*v.z + v.w*v.w;
    __shared__ float red[256];
    red[tid] = ss; __syncthreads();
    for (int of = 128; of > 0; of >>= 1) {
        if (tid < of) red[tid] += red[tid + of];
        __syncthreads();
    }
    float scale = rsqrtf(red[0] * (1.0f / DMODEL) + 1e-5f);
    float4 ww = ((const float4*)w)[tid];
    float vv[4] = {v.x*scale*ww.x, v.y*scale*ww.y, v.z*scale*ww.z, v.w*scale*ww.w};
    long base = r * DMODEL + tid * 4;
    #pragma unroll
    for (int e = 0; e < 4; e++) {
        __nv_bfloat16 hi = __float2bfloat16(vv[e]);
        o[base + e] = hi;
        o[plane + base + e] = __float2bfloat16(vv[e] - __bfloat162float(hi));
    }
}

// ---------------- RoPE tables ----------------
__global__ void rope_tab(float* gc, float* gs) {
    int t = blockIdx.x, i = threadIdx.x;
    double inv = exp(-(double)i * (9.210340371976184 / 32.0));
    double ang = (double)(1024 + t) * inv;
    gc[t*32 + i] = (float)cos(ang) * RSCALE;
    gs[t*32 + i] = (float)sin(ang) * RSCALE;
}

// ---------------- RoPE apply + scatter (Q->bf16 planes, K/V->out + bf16 slabs) -------
__global__ __launch_bounds__(128) void rope_scatter(
    const float* __restrict__ qkv,
    __nv_bfloat16* __restrict__ acQ, long qPlane,
    float* __restrict__ oK, float* __restrict__ oV,
    __nv_bfloat16* __restrict__ kbl,   // layer slab: [2pl][2kv][2048][64], plane 262144
    __nv_bfloat16* __restrict__ vbl,   // layer slab: [2pl][2kv][128][2048], plane 524288
    const float* __restrict__ gc, const float* __restrict__ gs)
{
    int t = blockIdx.x, tid = threadIdx.x;
    #pragma unroll
    for (int p = tid; p < 512; p += 128) {
        int h = p >> 5, i = p & 31;
        float c = gc[t*32 + i], s = gs[t*32 + i];
        int b = t*1280 + h*64 + i;
        float x1 = qkv[b], x2 = qkv[b + 32];
        float y1 = x1*c - x2*s, y2 = x2*c + x1*s;
        int ob = t*1024 + h*64 + i;
        __nv_bfloat16 h1 = __float2bfloat16(y1);
        acQ[ob] = h1;
        acQ[qPlane + ob] = __float2bfloat16(y1 - __bfloat162float(h1));
        __nv_bfloat16 h2 = __float2bfloat16(y2);
        acQ[ob + 32] = h2;
        acQ[qPlane + ob + 32] = __float2bfloat16(y2 - __bfloat162float(h2));
    }
    if (tid < 64) {
        int kv = tid >> 5, i = tid & 31;
        float c = gc[t*32 + i], s = gs[t*32 + i];
        int b = t*1280 + 1024 + kv*64 + i;
        float x1 = qkv[b], x2 = qkv[b + 32];
        float y1 = x1*c - x2*s, y2 = x2*c + x1*s;
        oK[(long)(kv*64 + i     ) * KVLEN + 1024 + t] = y1;
        oK[(long)(kv*64 + i + 32) * KVLEN + 1024 + t] = y2;
        long kidx = (long)kv * 131072 + (long)(1024 + t) * 64 + i;
        __nv_bfloat16 h1 = __float2bfloat16(y1);
        kbl[kidx] = h1;
        kbl[262144 + kidx] = __float2bfloat16(y1 - __bfloat162float(h1));
        __nv_bfloat16 h2 = __float2bfloat16(y2);
        kbl[kidx + 32] = h2;
        kbl[262144 + kidx + 32] = __float2bfloat16(y2 - __bfloat162float(h2));
    }
    {
        int kv = tid >> 6, d = tid & 63;
        float val = qkv[t*1280 + 1152 + tid];
        oV[(long)(kv*KVLEN + 1024 + t) * 64 + d] = val;
        long vidx = (long)kv * 262144 + (long)d * 2048 + 1024 + t;
        __nv_bfloat16 hv = __float2bfloat16(val);
        vbl[vidx] = hv;
        vbl[524288 + vidx] = __float2bfloat16(val - __bfloat162float(hv));
    }
}

// ---------------- softmax -> bf16 hi/lo directly ----------------
__global__ __launch_bounds__(256) void softmax_bf(
    const float* __restrict__ S, const float* __restrict__ mf,
    __nv_bfloat16* __restrict__ P, long plane)
{
    long r = blockIdx.x;
    int t = (int)(r & 1023);
    float flag = mf[0];
    const float* row = S + r * KVLEN;
    int tid = threadIdx.x;
    float vals[8];
    float mx = -1e30f;
    #pragma unroll
    for (int j = 0; j < 8; j++) {
        int s = tid + j*256;
        float m = (s > t) ? (-128.0f * flag) : 0.0f;
        vals[j] = row[s] + m;
        mx = fmaxf(mx, vals[j]);
    }
    __shared__ float red[256];
    red[tid] = mx; __syncthreads();
    for (int of = 128; of > 0; of >>= 1) {
        if (tid < of) red[tid] = fmaxf(red[tid], red[tid + of]);
        __syncthreads();
    }
    mx = red[0]; __syncthreads();
    float sum = 0.f;
    #pragma unroll
    for (int j = 0; j < 8; j++) { vals[j] = expf(vals[j] - mx); sum += vals[j]; }
    red[tid] = sum; __syncthreads();
    for (int of = 128; of > 0; of >>= 1) {
        if (tid < of) red[tid] += red[tid + of];
        __syncthreads();
    }
    float inv = 1.0f / red[0];
    long base = r * KVLEN;
    #pragma unroll
    for (int j = 0; j < 8; j++) {
        float v = vals[j] * inv;
        long o = base + tid + j*256;
        __nv_bfloat16 hi = __float2bfloat16(v);
        P[o] = hi;
        P[plane + o] = __float2bfloat16(v - __bfloat162float(hi));
    }
}

// ---------------- silu(gate)*up -> bf16 hi/lo ----------------
__global__ void silu_mul_bf(const float* __restrict__ gu,
                            __nv_bfloat16* __restrict__ o, long plane, int n4)
{
    int i = blockIdx.x * blockDim.x + threadIdx.x;
    if (i >= n4) return;                 // n4 = 1024*640
    int t = i / 640, c4 = i - t * 640;
    float4 a = ((const float4*)gu)[(long)t * 1280 + c4];
    float4 b = ((const float4*)gu)[(long)t * 1280 + 640 + c4];
    float r[4];
    r[0] = a.x / (1.f + expf(-a.x)) * b.x;
    r[1] = a.y / (1.f + expf(-a.y)) * b.y;
    r[2] = a.z / (1.f + expf(-a.z)) * b.z;
    r[3] = a.w / (1.f + expf(-a.w)) * b.w;
    long base = (long)t * 2560 + c4 * 4;
    #pragma unroll
    for (int e = 0; e < 4; e++) {
        __nv_bfloat16 hi = __float2bfloat16(r[e]);
        o[base + e] = hi;
        o[plane + base + e] = __float2bfloat16(r[e] - __bfloat162float(hi));
    }
}

__global__ void tanh_quant(float* z, int n) {
    int i = blockIdx.x * blockDim.x + threadIdx.x;
    if (i >= n) return;
    float t = tanhf(z[i]);
    float r = rintf(t * 4.0f) * 0.25f;
    z[i] = t + (r - t);
}

__global__ void copy_f4(float* __restrict__ dst, const float* __restrict__ src, int n4) {
    int i = blockIdx.x * blockDim.x + threadIdx.x;
    if (i < n4) ((float4*)dst)[i] = ((const float4*)src)[i];
}

__global__ void build_h(float* __restrict__ h, const float* __restrict__ x,
                        const float* __restrict__ f, const float* __restrict__ feat,
                        float* __restrict__ lmh)
{
    int i = blockIdx.x * 256 + threadIdx.x;
    int row = i >> 10, col = i & 1023;
    if (row < 256) h[i] = x[i];
    else {
        int j = ((row - 256) << 10) + col;
        h[i] = f[j] + feat[j];
    }
    if (row == 1023) lmh[col] = f[(767 << 10) + col];
}

__global__ void copy_caches(const float* __restrict__ kc, const float* __restrict__ vc,
                            float* __restrict__ oK, float* __restrict__ oV)
{
    int i = blockIdx.x * 256 + threadIdx.x;
    if (i < 524288) {
        int row = i >> 8, c4 = i & 255;
        ((float4*)oK)[(long)row * 512 + c4] = ((const float4*)kc)[i];
    } else {
        int j = i - 524288;
        int pair = j >> 14, off = j & 16383;
        ((float4*)oV)[(long)pair * 32768 + off] = ((const float4*)vc)[j];
    }
}

// ---------------- small heads ----------------
__global__ void gemv_dit(const float* __restrict__ lmh, const float* __restrict__ rh,
                         const float* __restrict__ W1, const float* __restrict__ W2,
                         float* __restrict__ out)
{
    int n = blockIdx.x * 256 + threadIdx.x;
    float acc = 0.f;
    for (int k = 0; k < 1024; k++) acc += lmh[k] * W1[k*1024 + n];
    for (int k = 0; k < 1024; k++) acc += rh[k]  * W2[k*1024 + n];
    out[n] = acc;
}

__global__ void gemv_gelu(const float* __restrict__ lmh, const float* __restrict__ W,
                          float* __restrict__ out)
{
    int n = blockIdx.x * 256 + threadIdx.x;
    float acc = 0.f;
    for (int k = 0; k < 1024; k++) acc += lmh[k] * W[k*1024 + n];
    float x = acc;
    float tg = tanhf(0.7978845608028654f * (x + 0.044715f * x*x*x));
    out[n] = 0.5f * x * (1.0f + tg);
}

__global__ void stop_head_k(const float* __restrict__ sp, const float* __restrict__ W,
                            float* __restrict__ out)
{
    __shared__ float r0[256], r1[256];
    int tid = threadIdx.x;
    float a0 = 0.f, a1 = 0.f;
    for (int k = tid; k < 1024; k += 256) {
        float s = sp[k];
        a0 += s * W[2*k];
        a1 += s * W[2*k + 1];
    }
    r0[tid] = a0; r1[tid] = a1; __syncthreads();
    for (int of = 128; of > 0; of >>= 1) {
        if (tid < of) { r0[tid] += r0[tid + of]; r1[tid] += r1[tid + of]; }
        __syncthreads();
    }
    if (tid == 0) out[0] = (r1[0] > r0[0]) ? 1.0f : 0.0f;
}

// ---------------- jax.random.normal(key(42)), partitionable threefry ----------------
__device__ __forceinline__ float tf_normal(unsigned bits) {
    float f = __uint_as_float((bits >> 9) | 0x3F800000u) - 1.0f;
    const float lo = -0.99999994f;
    float u = f * 2.0f + lo;
    u = fmaxf(lo, u);
    float w = -log1pf(-u * u);
    float p;
    if (w < 5.0f) {
        w -= 2.5f;
        p = 2.81022636e-08f;
        p = fmaf(p, w, 3.43273939e-07f);
        p = fmaf(p, w, -3.5233877e-06f);
        p = fmaf(p, w, -4.39150654e-06f);
        p = fmaf(p, w, 0.00021858087f);
        p = fmaf(p, w, -0.00125372503f);
        p = fmaf(p, w, -0.00417768164f);
        p = fmaf(p, w, 0.246640727f);
        p = fmaf(p, w, 1.50140941f);
    } else {
        w = sqrtf(w) - 3.0f;
        p = -0.000200214257f;
        p = fmaf(p, w, 0.000100950558f);
        p = fmaf(p, w, 0.00134934322f);
        p = fmaf(p, w, -0.00367342844f);
        p = fmaf(p, w, 0.00573950773f);
        p = fmaf(p, w, -0.0076224613f);
        p = fmaf(p, w, 0.00943887047f);
        p = fmaf(p, w, 1.00167406f);
        p = fmaf(p, w, 2.83297682f);
    }
    return 1.41421356f * (p * u);
}

__global__ void rnd_k(float* out) {
    int i = threadIdx.x;
    unsigned x0 = 0u, x1 = (unsigned)i;
    const unsigned K0 = 0u, K1 = 42u, K2 = 0u ^ 42u ^ 0x1BD11BDAu;
    unsigned ks[3] = {K0, K1, K2};
    x0 += K0; x1 += K1;
    const int rot[5][4] = {{13,15,26,6},{17,29,16,24},{13,15,26,6},{17,29,16,24},{13,15,26,6}};
    #pragma unroll
    for (int r = 0; r < 5; r++) {
        #pragma unroll
        for (int j = 0; j < 4; j++) {
            x0 += x1;
            int d = rot[r][j];
            x1 = (x1 << d) | (x1 >> (32 - d));
            x1 ^= x0;
        }
        x0 += ks[(r + 1) % 3];
        x1 += ks[(r + 2) % 3] + (unsigned)(r + 1);
    }
    out[i] = tf_normal(x0 ^ x1);
}

// ---------------- host ----------------
extern "C" void kernel_launch(void* const* d_in, const int* in_sizes, int n_in,
                              void* d_out, int out_size)
{
    const float* hidden = (const float*)d_in[0];
    const float* feat   = (const float*)d_in[1];
    const float* kc     = (const float*)d_in[2];
    const float* vc     = (const float*)d_in[3];
    const float* mf     = (const float*)d_in[4];
    const float* ln1    = (const float*)d_in[5];
    const float* ln2    = (const float*)d_in[6];
    const float* qw     = (const float*)d_in[7];
    const float* kw     = (const float*)d_in[8];
    const float* vw     = (const float*)d_in[9];
    const float* ow     = (const float*)d_in[10];
    const float* gw     = (const float*)d_in[11];
    const float* uw     = (const float*)d_in[12];
    const float* dw     = (const float*)d_in[13];
    const float* bnw    = (const float*)d_in[14];
    const float* rnw    = (const float*)d_in[15];
    const float* fdw    = (const float*)d_in[16];
    const float* fuw    = (const float*)d_in[17];
    const float* ldw    = (const float*)d_in[18];
    const float* rdw    = (const float*)d_in[19];
    const float* spw    = (const float*)d_in[20];
    const float* shw    = (const float*)d_in[21];

    float* out = (float*)d_out;
    float* oK = out;
    float* oV = out + 4194304;
    float* oD = out + 8388608;
    float* oR = out + 8389632;
    float* oS = out + 8389760;

    float *h_, *x_, *q_, *qkv_, *gu_, *sc_, *z_, *f_, *lmh_, *rh_, *sp_, *tc_, *ts_;
    cudaGetSymbolAddress((void**)&h_,   g_h);
    cudaGetSymbolAddress((void**)&x_,   g_x);
    cudaGetSymbolAddress((void**)&q_,   g_q);
    cudaGetSymbolAddress((void**)&qkv_, g_qkv);
    cudaGetSymbolAddress((void**)&gu_,  g_gu);
    cudaGetSymbolAddress((void**)&sc_,  g_scores);
    cudaGetSymbolAddress((void**)&z_,   g_z);
    cudaGetSymbolAddress((void**)&f_,   g_f);
    cudaGetSymbolAddress((void**)&lmh_, g_lmh);
    cudaGetSymbolAddress((void**)&rh_,  g_rh);
    cudaGetSymbolAddress((void**)&sp_,  g_sp);
    cudaGetSymbolAddress((void**)&tc_,  g_cos);
    cudaGetSymbolAddress((void**)&ts_,  g_sin);

    __nv_bfloat16 *wqkv_, *wo_, *wgu_, *wd_, *ac_, *ps_, *kb_, *vb_;
    cudaGetSymbolAddress((void**)&wqkv_, g_wqkv);
    cudaGetSymbolAddress((void**)&wo_,   g_wo);
    cudaGetSymbolAddress((void**)&wgu_,  g_wgu);
    cudaGetSymbolAddress((void**)&wd_,   g_wd);
    cudaGetSymbolAddress((void**)&ac_,   g_ac);
    cudaGetSymbolAddress((void**)&ps_,   g_ps);
    cudaGetSymbolAddress((void**)&kb_,   g_kb);
    cudaGetSymbolAddress((void**)&vb_,   g_vb);

    cudaFuncSetAttribute(mma_gemm, cudaFuncAttributeMaxDynamicSharedMemorySize, MG_SMEM);

    copy_f4<<<1024, 256>>>(h_, hidden, 262144);
    copy_caches<<<4096, 256>>>(kc, vc, oK, oV);
    rope_tab<<<1024, 32>>>(tc_, ts_);
    zero_bf<<<65536, 256>>>(vb_, 16777216);   // zero all-layer V slabs incl. pad rows

    // one-time weight conversion
    const long QKV_PL = 1280L * 1024, O_PL = 1048576L, GU_PL = 5120L * 1024, D_PL = 2621440L;
    conv_w<<<dim3(32, 32, 16), 256>>>(qw, 1048576, wqkv_, 2*QKV_PL, QKV_PL, 0,    1024, 1024);
    conv_w<<<dim3(4,  32, 16), 256>>>(kw, 131072,  wqkv_, 2*QKV_PL, QKV_PL, 1024, 1024, 128);
    conv_w<<<dim3(4,  32, 16), 256>>>(vw, 131072,  wqkv_, 2*QKV_PL, QKV_PL, 1152, 1024, 128);
    conv_w<<<dim3(32, 32, 16), 256>>>(ow, 1048576, wo_,   2*O_PL,   O_PL,   0,    1024, 1024);
    conv_w<<<dim3(80, 32, 16), 256>>>(gw, 2621440, wgu_,  2*GU_PL,  GU_PL,  0,    1024, 2560);
    conv_w<<<dim3(80, 32, 16), 256>>>(uw, 2621440, wgu_,  2*GU_PL,  GU_PL,  2560, 1024, 2560);
    conv_w<<<dim3(32, 80, 16), 256>>>(dw, 2621440, wd_,   2*D_PL,   D_PL,   0,    2560, 1024);

    // one-time history cache conversion into all-layer bf16 slabs
    for (int l = 0; l < LTOT; l++) {
        // K hist: [2kv][64][1024] -> kb[l][pl][kv][s<1024][64]
        conv_t<<<dim3(32, 2, 2), 256>>>(kc + (long)l*131072, 65536,
            kb_ + (long)l*524288, 131072, 262144, 64, 1024, 64);
        // V hist: [2kv][1024][64] -> vb[l][pl][kv][d<64][s<1024] (ld 2048)
        conv_t<<<dim3(2, 32, 2), 256>>>(vc + (long)l*131072, 65536,
            vb_ + (long)l*1048576, 262144, 524288, 1024, 64, 2048);
    }

    const long PL_D  = 1048576;   // act plane 1024*1024
    const long PL_FF = 2621440;   // act plane 1024*2560
    const long PL_P  = 33554432;  // P plane 16*1024*2048

    for (int l = 0; l < LTOT; l++) {
        if (l == 12) {
            rms_rows<<<1024, 256>>>(h_, bnw, x_);
            sgemm<<<dim3(1, 12, 1), 256>>>(x_ + 256*1024, 1024, 0, fdw, 32, 0, 1,
                                           z_, 32, 0, 768, 32, 1024, 0);
            tanh_quant<<<96, 256>>>(z_, 24576);
            sgemm<<<dim3(16, 12, 1), 256>>>(z_, 32, 0, fuw, 1024, 0, 1,
                                            f_, 1024, 0, 768, 1024, 32, 0);
            build_h<<<4096, 256>>>(h_, x_, f_, feat, lmh_);
        }
        float* lK = oK + (long)l * 262144;                 // fp32 out [2][64][2048]
        float* lV = oV + (long)l * 262144;                 // fp32 out [2][2048][64]
        __nv_bfloat16* kbl = kb_ + (long)l * 524288;
        __nv_bfloat16* vbl = vb_ + (long)l * 1048576;

        rms_bf<<<1024, 256>>>(h_, ln1 + l*1024, ac_, PL_D);
        mma_gemm<<<dim3(10, 8, 1), 256, MG_SMEM>>>(ac_, PL_D, 1024, 0,
            wqkv_ + (long)l*2*QKV_PL, QKV_PL, 1024, 0, 1,
            qkv_, 1280, 0, 1024, 1280, 0);
        rope_scatter<<<1024, 128>>>(qkv_, ac_, PL_D, lK, lV, kbl, vbl, tc_, ts_);
        // scores[h] = Q_h [1024x64] @ K_kv^T -> [1024][2048] fp32
        mma_gemm<<<dim3(16, 8, 16), 256, MG_SMEM>>>(ac_, PL_D, 1024, 64,
            kbl, 262144, 64, 131072, 8,
            sc_, 2048, 2097152, 64, 2048, 0);
        softmax_bf<<<16384, 256>>>(sc_, mf, ps_, PL_P);
        // out[h] = P_h [1024x2048] @ V_kv -> q_ cols h*64..h*64+63
        mma_gemm<<<dim3(1, 8, 16), 256, MG_SMEM>>>(ps_, PL_P, 2048, 2097152,
            vbl, 524288, 2048, 262144, 8,
            q_, 1024, 64, 2048, 64, 0);
        conv_act<<<4096, 256>>>(q_, ac_, PL_D, 1048576);
        mma_gemm<<<dim3(8, 8, 1), 256, MG_SMEM>>>(ac_, PL_D, 1024, 0,
            wo_ + (long)l*2*O_PL, O_PL, 1024, 0, 1,
            h_, 1024, 0, 1024, 1024, 1);
        rms_bf<<<1024, 256>>>(h_, ln2 + l*1024, ac_, PL_D);
        mma_gemm<<<dim3(40, 8, 1), 256, MG_SMEM>>>(ac_, PL_D, 1024, 0,
            wgu_ + (long)l*2*GU_PL, GU_PL, 1024, 0, 1,
            gu_, 5120, 0, 1024, 5120, 0);
        silu_mul_bf<<<2560, 256>>>(gu_, ac_, PL_FF, 655360);
        mma_gemm<<<dim3(8, 8, 1), 256, MG_SMEM>>>(ac_, PL_FF, 2560, 0,
            wd_ + (long)l*2*D_PL, D_PL, 2560, 0, 1,
            h_, 1024, 0, 2560, 1024, 1);
    }

    rms_rows<<<1, 256>>>(h_ + 1023*1024, rnw, rh_);
    gemv_dit<<<4, 256>>>(lmh_, rh_, ldw, rdw, oD);
    gemv_gelu<<<4, 256>>>(lmh_, spw, sp_);
    stop_head_k<<<1, 256>>>(sp_, shw, oS);
    rnd_k<<<1, 128>>>(oR);
}